// round 3
// baseline (speedup 1.0000x reference)
#include <cuda_runtime.h>
#include <math.h>

// ---------------- problem constants ----------------
#define BATCH 8
#define SEQ   512
#define EMB   1024
#define HEADS 16
#define HDIM  64
#define TOK   (BATCH*SEQ)     // 4096
#define DFF   4096
#define NS    4
#define NM    2
#define NEXP  6

// ---------------- output layout (tuple concatenated) ----------------
#define OFF_LOSS 4194304
#define OFF_SM   4194305
#define OFF_IM   4210689
#define OFF_AW   4218881

// ---------------- scratch (device globals: no allocation allowed) ----------------
__device__ float g_xn  [TOK*EMB];
__device__ float g_qkv [TOK*3*EMB];
__device__ float g_attn[(size_t)BATCH*HEADS*SEQ*SEQ];   // 128 MB
__device__ float g_ctx [TOK*EMB];
__device__ float g_x1  [TOK*EMB];
__device__ float g_xn2 [TOK*EMB];
__device__ float g_h   [(size_t)TOK*DFF];               // 64 MB
__device__ float g_comb[TOK*EMB];
__device__ float g_x2  [TOK*EMB];
__device__ float g_xn3 [TOK*EMB];
__device__ float g_masks[TOK*NEXP];
__device__ float g_acc [12];   // importance[6], load[6]

// buffer ids for generic kernels (avoids any host-side symbol addressing)
#define BUF_XN   0
#define BUF_QKV  1
#define BUF_CTX  3
#define BUF_X1   4
#define BUF_XN2  5
#define BUF_H    6
#define BUF_COMB 7
#define BUF_X2   8
#define BUF_XN3  9
#define BUF_NONE -1

__device__ __forceinline__ float* buf_ptr(int id) {
    switch (id) {
        case BUF_XN:   return g_xn;
        case BUF_QKV:  return g_qkv;
        case BUF_CTX:  return g_ctx;
        case BUF_X1:   return g_x1;
        case BUF_XN2:  return g_xn2;
        case BUF_H:    return g_h;
        case BUF_COMB: return g_comb;
        case BUF_X2:   return g_x2;
        case BUF_XN3:  return g_xn3;
        default:       return nullptr;
    }
}

// ---------------- layernorm: one block per row ----------------
__global__ void ln_kernel(const float* __restrict__ xExt, int xId,
                          const float* __restrict__ w, const float* __restrict__ b,
                          int outId)
{
    const float* x = xExt ? xExt : buf_ptr(xId);
    float* out = buf_ptr(outId);
    int row = blockIdx.x;
    int t = threadIdx.x;  // 256
    const float* xr = x + (size_t)row * EMB;
    float v[4]; float s = 0.f, s2 = 0.f;
#pragma unroll
    for (int i = 0; i < 4; i++) { v[i] = xr[t + i*256]; s += v[i]; s2 += v[i]*v[i]; }
    __shared__ float rs[256], rq[256];
    rs[t] = s; rq[t] = s2; __syncthreads();
    for (int o = 128; o > 0; o >>= 1) {
        if (t < o) { rs[t] += rs[t+o]; rq[t] += rq[t+o]; }
        __syncthreads();
    }
    float mean = rs[0] * (1.0f/EMB);
    float var  = rq[0] * (1.0f/EMB) - mean*mean;
    float inv  = rsqrtf(var + 1e-5f);
    float* orow = out + (size_t)row * EMB;
#pragma unroll
    for (int i = 0; i < 4; i++) {
        int c = t + i*256;
        orow[c] = (v[i]-mean)*inv*w[c] + b[c];
    }
}

// ---------------- generic TN GEMM: C[M,N] = A[M,K] * B[N,K]^T (+epilogues) ----------------
// grid: (N/128, M/128), 256 threads, 128x128x8 tiles, 8x8 microtile, double-buffered smem.
__device__ __forceinline__ float gelu_exact(float v) {
    return 0.5f * v * (1.0f + erff(v * 0.70710678118654752f));
}

__global__ void gemm_tn_kernel(int Aid, int lda,
                               const float* __restrict__ Bw, int ldb,
                               const float* __restrict__ bias,
                               float* __restrict__ Cext, int Cid, int ldc, int K,
                               const float* __restrict__ resExt, int resId,
                               int maskCol, int doGelu, int accumulate)
{
    const float* A = buf_ptr(Aid);
    float* C = Cext ? Cext : buf_ptr(Cid);
    const float* res = resExt ? resExt : buf_ptr(resId);

    __shared__ float As[2][8][128];
    __shared__ float Bs[2][8][128];
    int m0 = blockIdx.y * 128, n0 = blockIdx.x * 128;
    int tid = threadIdx.x;
    int tx = tid & 15, ty = tid >> 4;
    float acc[8][8];
#pragma unroll
    for (int i = 0; i < 8; i++)
#pragma unroll
        for (int j = 0; j < 8; j++) acc[i][j] = 0.f;

    int lrow = tid >> 1;          // 0..127
    int lk4  = (tid & 1) * 4;     // 0 or 4
    const float* Ap = A  + (size_t)(m0 + lrow) * lda + lk4;
    const float* Bp = Bw + (size_t)(n0 + lrow) * ldb + lk4;

    {
        float4 a4 = *(const float4*)(Ap);
        float4 b4 = *(const float4*)(Bp);
        As[0][lk4+0][lrow] = a4.x; As[0][lk4+1][lrow] = a4.y;
        As[0][lk4+2][lrow] = a4.z; As[0][lk4+3][lrow] = a4.w;
        Bs[0][lk4+0][lrow] = b4.x; Bs[0][lk4+1][lrow] = b4.y;
        Bs[0][lk4+2][lrow] = b4.z; Bs[0][lk4+3][lrow] = b4.w;
    }
    __syncthreads();

    int buf = 0;
    for (int k0 = 8; k0 <= K; k0 += 8) {
        float4 a4n, b4n;
        int havenext = (k0 < K);
        if (havenext) {
            a4n = *(const float4*)(Ap + k0);
            b4n = *(const float4*)(Bp + k0);
        }
#pragma unroll
        for (int k = 0; k < 8; k++) {
            float ar[8], br[8];
            *(float4*)&ar[0] = *(const float4*)&As[buf][k][ty*8];
            *(float4*)&ar[4] = *(const float4*)&As[buf][k][ty*8+4];
            *(float4*)&br[0] = *(const float4*)&Bs[buf][k][tx*8];
            *(float4*)&br[4] = *(const float4*)&Bs[buf][k][tx*8+4];
#pragma unroll
            for (int i = 0; i < 8; i++)
#pragma unroll
                for (int j = 0; j < 8; j++)
                    acc[i][j] += ar[i] * br[j];
        }
        if (havenext) {
            int nb = buf ^ 1;
            As[nb][lk4+0][lrow] = a4n.x; As[nb][lk4+1][lrow] = a4n.y;
            As[nb][lk4+2][lrow] = a4n.z; As[nb][lk4+3][lrow] = a4n.w;
            Bs[nb][lk4+0][lrow] = b4n.x; Bs[nb][lk4+1][lrow] = b4n.y;
            Bs[nb][lk4+2][lrow] = b4n.z; Bs[nb][lk4+3][lrow] = b4n.w;
            __syncthreads();
            buf = nb;
        }
    }

#pragma unroll
    for (int i = 0; i < 8; i++) {
        int m = m0 + ty*8 + i;
        float rsc = (maskCol >= 0) ? g_masks[(size_t)m * NEXP + maskCol] : 1.0f;
#pragma unroll
        for (int j = 0; j < 8; j++) {
            int n = n0 + tx*8 + j;
            float v = acc[i][j] + bias[n];
            if (doGelu) v = gelu_exact(v);
            v *= rsc;
            if (res) v += res[(size_t)m * ldc + n];
            float* cp = C + (size_t)m * ldc + n;
            if (accumulate) *cp += v; else *cp = v;
        }
    }
}

// ---------------- attention scores: per (b,h), 64x64 tile, K=64 ----------------
// grid (SEQ/64, SEQ/64, B*H), 256 threads
__global__ void scores_kernel()
{
    int bh = blockIdx.z; int b = bh >> 4, h = bh & 15;
    int q0 = blockIdx.y * 64, k0 = blockIdx.x * 64;
    __shared__ float Qs[64][65], Ks[64][65];
    int tid = threadIdx.x;
    const float* qbase = g_qkv + ((size_t)(b*SEQ) + q0) * 3072 + h*64;
    const float* kbase = g_qkv + ((size_t)(b*SEQ) + k0) * 3072 + 1024 + h*64;
#pragma unroll
    for (int i = 0; i < 4; i++) {
        int lin = tid + i*256;            // float4 index
        int r = lin >> 4, c4 = (lin & 15) * 4;
        float4 qa = *(const float4*)(qbase + (size_t)r*3072 + c4);
        Qs[r][c4+0]=qa.x; Qs[r][c4+1]=qa.y; Qs[r][c4+2]=qa.z; Qs[r][c4+3]=qa.w;
        float4 ka = *(const float4*)(kbase + (size_t)r*3072 + c4);
        Ks[r][c4+0]=ka.x; Ks[r][c4+1]=ka.y; Ks[r][c4+2]=ka.z; Ks[r][c4+3]=ka.w;
    }
    __syncthreads();
    int tx = tid & 15, ty = tid >> 4;
    float acc[4][4];
#pragma unroll
    for (int i=0;i<4;i++)
#pragma unroll
        for (int j=0;j<4;j++) acc[i][j]=0.f;
#pragma unroll 8
    for (int k = 0; k < 64; k++) {
        float a[4], bb[4];
#pragma unroll
        for (int i=0;i<4;i++) a[i]  = Qs[ty*4+i][k];
#pragma unroll
        for (int j=0;j<4;j++) bb[j] = Ks[tx*4+j][k];
#pragma unroll
        for (int i=0;i<4;i++)
#pragma unroll
            for (int j=0;j<4;j++) acc[i][j] += a[i]*bb[j];
    }
    float* out = g_attn + ((size_t)bh*SEQ + q0)*SEQ + k0;
#pragma unroll
    for (int i=0;i<4;i++)
#pragma unroll
        for (int j=0;j<4;j++)
            out[(size_t)(ty*4+i)*SEQ + tx*4+j] = acc[i][j] * 0.125f;
}

// ---------------- softmax over last dim (512), one block per row ----------------
__global__ void softmax_kernel()
{
    size_t base = (size_t)blockIdx.x * SEQ;
    int t = threadIdx.x; // 256
    float v0 = g_attn[base+t], v1 = g_attn[base+t+256];
    __shared__ float red[256];
    red[t] = fmaxf(v0, v1); __syncthreads();
    for (int o = 128; o > 0; o >>= 1) {
        if (t < o) red[t] = fmaxf(red[t], red[t+o]);
        __syncthreads();
    }
    float mx = red[0]; __syncthreads();
    float e0 = expf(v0 - mx), e1 = expf(v1 - mx);
    red[t] = e0 + e1; __syncthreads();
    for (int o = 128; o > 0; o >>= 1) {
        if (t < o) red[t] += red[t+o];
        __syncthreads();
    }
    float inv = 1.0f / red[0];
    g_attn[base+t] = e0*inv; g_attn[base+t+256] = e1*inv;
}

// ---------------- attn mean over heads -> attn_weights ----------------
__global__ void attnmean_kernel(float* __restrict__ out)
{
    size_t lin = (size_t)blockIdx.x * 256 + threadIdx.x;  // over B*S*S
    int b = (int)(lin / ((size_t)SEQ*SEQ));
    size_t r = lin % ((size_t)SEQ*SEQ);
    const float* p = g_attn + (size_t)b*HEADS*SEQ*SEQ + r;
    float s = 0.f;
#pragma unroll
    for (int h = 0; h < HEADS; h++) s += p[(size_t)h*SEQ*SEQ];
    out[lin] = s * (1.0f/HEADS);
}

// ---------------- ctx = attn @ V per (b,h) ----------------
// grid (SEQ/64, B*H), 256 threads
__global__ void ctx_kernel()
{
    int bh = blockIdx.y; int b = bh >> 4, h = bh & 15;
    int q0 = blockIdx.x * 64;
    __shared__ float As[16][64];  // As[k][q]
    __shared__ float Vs[16][64];  // Vs[k][d]
    const float* arow  = g_attn + ((size_t)bh*SEQ + q0) * SEQ;
    const float* vbase = g_qkv + (size_t)(b*SEQ) * 3072 + 2048 + h*64;
    int tid = threadIdx.x, tx = tid & 15, ty = tid >> 4;
    float acc[4][4];
#pragma unroll
    for (int i=0;i<4;i++)
#pragma unroll
        for (int j=0;j<4;j++) acc[i][j]=0.f;

    for (int k0 = 0; k0 < SEQ; k0 += 16) {
        {
            int q = tid >> 2, k4 = (tid & 3) * 4;
            float4 a4 = *(const float4*)(arow + (size_t)q*SEQ + k0 + k4);
            As[k4+0][q]=a4.x; As[k4+1][q]=a4.y; As[k4+2][q]=a4.z; As[k4+3][q]=a4.w;
            int k = tid >> 4, d4 = (tid & 15) * 4;
            float4 v4 = *(const float4*)(vbase + (size_t)(k0+k)*3072 + d4);
            *(float4*)&Vs[k][d4] = v4;
        }
        __syncthreads();
#pragma unroll
        for (int k = 0; k < 16; k++) {
            float a[4], bb[4];
#pragma unroll
            for (int i=0;i<4;i++) a[i]  = As[k][ty*4+i];
#pragma unroll
            for (int j=0;j<4;j++) bb[j] = Vs[k][tx*4+j];
#pragma unroll
            for (int i=0;i<4;i++)
#pragma unroll
                for (int j=0;j<4;j++) acc[i][j] += a[i]*bb[j];
        }
        __syncthreads();
    }
    float* out = g_ctx + ((size_t)(b*SEQ) + q0) * EMB + h*64;
#pragma unroll
    for (int i=0;i<4;i++)
#pragma unroll
        for (int j=0;j<4;j++)
            out[(size_t)(ty*4+i)*EMB + tx*4+j] = acc[i][j];
}

// ---------------- routers: one block per token ----------------
__global__ void zero_acc_kernel() { if (threadIdx.x < 12) g_acc[threadIdx.x] = 0.f; }

__global__ void router_kernel(const float* __restrict__ srw, const float* __restrict__ srb,
                              const float* __restrict__ irw, const float* __restrict__ irb,
                              float* __restrict__ smask, float* __restrict__ imask)
{
    int m = blockIdx.x, t = threadIdx.x;  // 128 threads
    const float* xr = g_xn2 + (size_t)m * EMB;
    float p[6] = {0,0,0,0,0,0};
    for (int e = t; e < EMB; e += 128) {
        float xv = xr[e];
        p[0] += xv * srw[e];
        p[1] += xv * srw[EMB + e];
        p[2] += xv * srw[2*EMB + e];
        p[3] += xv * srw[3*EMB + e];
        p[4] += xv * irw[e];
        p[5] += xv * irw[EMB + e];
    }
    __shared__ float red[6][128];
#pragma unroll
    for (int n = 0; n < 6; n++) red[n][t] = p[n];
    __syncthreads();
    for (int o = 64; o > 0; o >>= 1) {
        if (t < o)
#pragma unroll
            for (int n = 0; n < 6; n++) red[n][t] += red[n][t+o];
        __syncthreads();
    }
    if (t == 0) {
        float lg[6];
        for (int n = 0; n < 4; n++) lg[n] = red[n][0] + srb[n];
        lg[4] = red[4][0] + irb[0];
        lg[5] = red[5][0] + irb[1];
        // shared softmax over 4
        float mx = lg[0];
        for (int n = 1; n < 4; n++) mx = fmaxf(mx, lg[n]);
        float pp[4], sum = 0.f;
        for (int n = 0; n < 4; n++) { pp[n] = expf(lg[n]-mx); sum += pp[n]; }
        float invs = 1.0f/sum;
        for (int n = 0; n < 4; n++) pp[n] *= invs;
        // top-2 (ties -> lowest index, matching jax top_k)
        int i1 = 0;
        for (int n = 1; n < 4; n++) if (pp[n] > pp[i1]) i1 = n;
        int i2 = -1;
        for (int n = 0; n < 4; n++) if (n != i1 && (i2 < 0 || pp[n] > pp[i2])) i2 = n;
        // image softmax over 2 (both always selected with K=2)
        float mxi = fmaxf(lg[4], lg[5]);
        float e4 = expf(lg[4]-mxi), e5 = expf(lg[5]-mxi);
        float si = 1.0f/(e4+e5);
        float pi0 = e4*si, pi1 = e5*si;
        for (int n = 0; n < 4; n++) {
            float mv = (n == i1 || n == i2) ? pp[n] : 0.f;
            g_masks[(size_t)m*NEXP + n] = mv;
            smask[(size_t)m*NS + n]     = mv;
        }
        g_masks[(size_t)m*NEXP + 4] = pi0; g_masks[(size_t)m*NEXP + 5] = pi1;
        imask[(size_t)m*NM + 0] = pi0;     imask[(size_t)m*NM + 1] = pi1;
        for (int n = 0; n < 4; n++) atomicAdd(&g_acc[n], pp[n]);
        atomicAdd(&g_acc[4], pi0); atomicAdd(&g_acc[5], pi1);
        atomicAdd(&g_acc[6+i1], 1.0f); atomicAdd(&g_acc[6+i2], 1.0f);
        atomicAdd(&g_acc[10], 1.0f);   atomicAdd(&g_acc[11], 1.0f);
    }
}

__global__ void loss_kernel(float* __restrict__ out)
{
    if (threadIdx.x == 0 && blockIdx.x == 0) {
        const float inv = 1.0f / (float)TOK;
        float ls = 0.f, li = 0.f;
        for (int n = 0; n < 4; n++) ls += (g_acc[n]*inv) * (g_acc[6+n]*inv);
        for (int n = 4; n < 6; n++) li += (g_acc[n]*inv) * (g_acc[6+n]*inv);
        out[0] = 4.0f*ls + 2.0f*li;
    }
}

__global__ void add_kernel()   // x2 = x1 + comb
{
    size_t i = (size_t)blockIdx.x * 256 + threadIdx.x;
    g_x2[i] = g_x1[i] + g_comb[i];
}

// ---------------- launcher ----------------
extern "C" void kernel_launch(void* const* d_in, const int* in_sizes, int n_in,
                              void* d_out, int out_size)
{
    const float* x   = (const float*)d_in[0];
    const float* n1w = (const float*)d_in[1];
    const float* n1b = (const float*)d_in[2];
    const float* n2w = (const float*)d_in[3];
    const float* n2b = (const float*)d_in[4];
    const float* ipw = (const float*)d_in[5];
    const float* ipb = (const float*)d_in[6];
    const float* opw = (const float*)d_in[7];
    const float* opb = (const float*)d_in[8];
    const float* srw = (const float*)d_in[9];
    const float* srb = (const float*)d_in[10];
    const float* irw = (const float*)d_in[11];
    const float* irb = (const float*)d_in[12];
    const float* ew1 = (const float*)d_in[13];
    const float* eb1 = (const float*)d_in[14];
    const float* ew2 = (const float*)d_in[15];
    const float* eb2 = (const float*)d_in[16];
    const float* fw1 = (const float*)d_in[17];
    const float* fb1 = (const float*)d_in[18];
    const float* fw2 = (const float*)d_in[19];
    const float* fb2 = (const float*)d_in[20];

    float* out      = (float*)d_out;
    float* out_x    = out;
    float* out_loss = out + OFF_LOSS;
    float* out_sm   = out + OFF_SM;
    float* out_im   = out + OFF_IM;
    float* out_aw   = out + OFF_AW;

    // 1) LN1: xn = LN(x)
    ln_kernel<<<TOK, 256>>>(x, BUF_NONE, n1w, n1b, BUF_XN);

    // 2) QKV = xn @ ipw^T + ipb    [4096,3072], K=1024
    gemm_tn_kernel<<<dim3(3072/128, TOK/128), 256>>>(
        BUF_XN, EMB, ipw, EMB, ipb, nullptr, BUF_QKV, 3*EMB, EMB,
        nullptr, BUF_NONE, -1, 0, 0);

    // 3) scores
    scores_kernel<<<dim3(SEQ/64, SEQ/64, BATCH*HEADS), 256>>>();

    // 4) softmax in place
    softmax_kernel<<<BATCH*HEADS*SEQ, 256>>>();

    // 5) attn mean over heads -> output
    attnmean_kernel<<<(BATCH*SEQ*SEQ)/256, 256>>>(out_aw);

    // 6) ctx = attn @ V
    ctx_kernel<<<dim3(SEQ/64, BATCH*HEADS), 256>>>();

    // 7) x1 = x + ctx @ opw^T + opb
    gemm_tn_kernel<<<dim3(EMB/128, TOK/128), 256>>>(
        BUF_CTX, EMB, opw, EMB, opb, nullptr, BUF_X1, EMB, EMB,
        x, BUF_NONE, -1, 0, 0);

    // 8) LN2: xn2 = LN(x1)
    ln_kernel<<<TOK, 256>>>(nullptr, BUF_X1, n2w, n2b, BUF_XN2);

    // 9-11) routers + loss
    zero_acc_kernel<<<1, 32>>>();
    router_kernel<<<TOK, 128>>>(srw, srb, irw, irb, out_sm, out_im);
    loss_kernel<<<1, 32>>>(out_loss);

    // 12) experts (dense, masked-accumulated combine)
    for (int n = 0; n < NEXP; n++) {
        const float* w1 = ew1 + (size_t)n * DFF * EMB;
        const float* b1 = eb1 + (size_t)n * DFF;
        const float* w2 = ew2 + (size_t)n * EMB * DFF;
        const float* b2 = eb2 + (size_t)n * EMB;
        // h = gelu(xn2 @ w1^T + b1)   [4096,4096], K=1024
        gemm_tn_kernel<<<dim3(DFF/128, TOK/128), 256>>>(
            BUF_XN2, EMB, w1, EMB, b1, nullptr, BUF_H, DFF, EMB,
            nullptr, BUF_NONE, -1, 1, 0);
        // comb (+)= mask[:,n] * (h @ w2^T + b2)   [4096,1024], K=4096
        gemm_tn_kernel<<<dim3(EMB/128, TOK/128), 256>>>(
            BUF_H, DFF, w2, DFF, b2, nullptr, BUF_COMB, EMB, DFF,
            nullptr, BUF_NONE, n, 0, n > 0 ? 1 : 0);
    }

    // 13) x2 = x1 + comb
    add_kernel<<<(TOK*EMB)/256, 256>>>();

    // 14) LN3 (reuses norm2 params)
    ln_kernel<<<TOK, 256>>>(nullptr, BUF_X2, n2w, n2b, BUF_XN3);

    // 15) fh = gelu(xn3 @ fw1^T + fb1)   [4096,4096], K=1024
    gemm_tn_kernel<<<dim3(DFF/128, TOK/128), 256>>>(
        BUF_XN3, EMB, fw1, EMB, fb1, nullptr, BUF_H, DFF, EMB,
        nullptr, BUF_NONE, -1, 1, 0);

    // 16) out_x = x2 + fh @ fw2^T + fb2   [4096,1024], K=4096
    gemm_tn_kernel<<<dim3(EMB/128, TOK/128), 256>>>(
        BUF_H, DFF, fw2, DFF, fb2, out_x, BUF_NONE, EMB, DFF,
        nullptr, BUF_X2, -1, 0, 0);
}

// round 6
// speedup vs baseline: 1.5537x; 1.5537x over previous
#include <cuda_runtime.h>
#include <cuda_bf16.h>
#include <mma.h>
#include <math.h>

using namespace nvcuda;

// ---------------- problem constants ----------------
#define BATCH 8
#define SEQ   512
#define EMB   1024
#define HEADS 16
#define HDIM  64
#define TOK   (BATCH*SEQ)     // 4096
#define DFF   4096
#define NS    4
#define NM    2
#define NEXP  6

// ---------------- output layout (tuple concatenated) ----------------
#define OFF_LOSS 4194304
#define OFF_SM   4194305
#define OFF_IM   4210689
#define OFF_AW   4218881

// ---------------- scratch (device globals: no allocation allowed) ----------------
__device__ float g_xn  [TOK*EMB];
__device__ float g_qkv [TOK*3*EMB];
__device__ float g_attn[(size_t)BATCH*HEADS*SEQ*SEQ];   // 128 MB
__device__ float g_ctx [TOK*EMB];
__device__ float g_x1  [TOK*EMB];
__device__ float g_xn2 [TOK*EMB];
__device__ float g_h   [(size_t)TOK*DFF];               // 64 MB
__device__ float g_comb[TOK*EMB];
__device__ float g_x2  [TOK*EMB];
__device__ float g_xn3 [TOK*EMB];
__device__ float g_masks[TOK*NEXP];
__device__ float g_acc [12];   // importance[6], load[6]

// buffer ids for generic kernels (avoids any host-side symbol addressing)
#define BUF_XN   0
#define BUF_QKV  1
#define BUF_CTX  3
#define BUF_X1   4
#define BUF_XN2  5
#define BUF_H    6
#define BUF_COMB 7
#define BUF_X2   8
#define BUF_XN3  9
#define BUF_NONE -1

__device__ __forceinline__ float* buf_ptr(int id) {
    switch (id) {
        case BUF_XN:   return g_xn;
        case BUF_QKV:  return g_qkv;
        case BUF_CTX:  return g_ctx;
        case BUF_X1:   return g_x1;
        case BUF_XN2:  return g_xn2;
        case BUF_H:    return g_h;
        case BUF_COMB: return g_comb;
        case BUF_X2:   return g_x2;
        case BUF_XN3:  return g_xn3;
        default:       return nullptr;
    }
}

// ---------------- layernorm: one block per row ----------------
__global__ void ln_kernel(const float* __restrict__ xExt, int xId,
                          const float* __restrict__ w, const float* __restrict__ b,
                          int outId)
{
    const float* x = xExt ? xExt : buf_ptr(xId);
    float* out = buf_ptr(outId);
    int row = blockIdx.x;
    int t = threadIdx.x;  // 256
    const float* xr = x + (size_t)row * EMB;
    float v[4]; float s = 0.f, s2 = 0.f;
#pragma unroll
    for (int i = 0; i < 4; i++) { v[i] = xr[t + i*256]; s += v[i]; s2 += v[i]*v[i]; }
    __shared__ float rs[256], rq[256];
    rs[t] = s; rq[t] = s2; __syncthreads();
    for (int o = 128; o > 0; o >>= 1) {
        if (t < o) { rs[t] += rs[t+o]; rq[t] += rq[t+o]; }
        __syncthreads();
    }
    float mean = rs[0] * (1.0f/EMB);
    float var  = rq[0] * (1.0f/EMB) - mean*mean;
    float inv  = rsqrtf(var + 1e-5f);
    float* orow = out + (size_t)row * EMB;
#pragma unroll
    for (int i = 0; i < 4; i++) {
        int c = t + i*256;
        orow[c] = (v[i]-mean)*inv*w[c] + b[c];
    }
}

__device__ __forceinline__ float gelu_exact(float v) {
    return 0.5f * v * (1.0f + erff(v * 0.70710678118654752f));
}

// ============================================================================
// WMMA tensor-core TN GEMM with 2-term bf16 split (fp32-like accuracy):
//   C[M,N] = A[M,K] * B[N,K]^T  computed as Ah*Bh + Ah*Bl + Al*Bh
// 128x128 block tile, BK=16, 8 warps (each 32x64), wmma 16x16x16 bf16->fp32.
// No inline asm anywhere.
// ============================================================================

// per-stage smem (bf16, rows of 24 elems = 48B, multiple of 16B for wmma ldm):
//   Ahi @ 0, Alo @ 6144, Bhi @ 12288, Blo @ 18432  -> 24576 B/stage, 2 stages = 48 KB
#define TCS_LD     24
#define TCS_AHI    0
#define TCS_ALO    6144
#define TCS_BHI    12288
#define TCS_BLO    18432
#define TCS_STAGE  24576

__device__ __forceinline__ void split_store(float4 v, __nv_bfloat16* hi, __nv_bfloat16* lo)
{
    float f[4] = {v.x, v.y, v.z, v.w};
#pragma unroll
    for (int j = 0; j < 4; j++) {
        __nv_bfloat16 h = __float2bfloat16_rn(f[j]);
        hi[j] = h;
        lo[j] = __float2bfloat16_rn(f[j] - __bfloat162float(h));
    }
}

__global__ void __launch_bounds__(256, 1)
gemm_tc_kernel(int Aid, int lda,
               const float* __restrict__ Bw, int ldb,
               const float* __restrict__ bias,
               float* __restrict__ Cext, int Cid, int ldc, int K,
               const float* __restrict__ resExt, int resId,
               int maskCol, int doGelu, int accumulate)
{
    const float* A = buf_ptr(Aid);
    float* C = Cext ? Cext : buf_ptr(Cid);
    const float* res = resExt ? resExt : buf_ptr(resId);

    __shared__ __align__(16) unsigned char sm[2*TCS_STAGE];   // 48 KB

    int m0 = blockIdx.y * 128, n0 = blockIdx.x * 128;
    int tid = threadIdx.x;
    int lane = tid & 31, warp = tid >> 5;
    int wm = (warp >> 1) * 32, wn = (warp & 1) * 64;

    // ---- per-thread fill mapping: 2 float4 per operand tile (128 rows x 16 k) ----
    int frow[2], fk[2];
#pragma unroll
    for (int i = 0; i < 2; i++) {
        int idx = tid*2 + i;
        frow[i] = idx >> 2;           // 0..127
        fk[i]   = (idx & 3) * 4;      // 0,4,8,12
    }
    const float* pA[2]; const float* pB[2];
#pragma unroll
    for (int i = 0; i < 2; i++) {
        pA[i] = A  + (size_t)(m0 + frow[i]) * lda + fk[i];
        pB[i] = Bw + (size_t)(n0 + frow[i]) * ldb + fk[i];
    }

    wmma::fragment<wmma::accumulator, 16, 16, 16, float> c_frag[2][4];
#pragma unroll
    for (int mi = 0; mi < 2; mi++)
#pragma unroll
        for (int nj = 0; nj < 4; nj++)
            wmma::fill_fragment(c_frag[mi][nj], 0.0f);

    int KT = K >> 4;

    // ---- prologue: fill stage 0 ----
    {
        unsigned char* sb = sm;
#pragma unroll
        for (int i = 0; i < 2; i++) {
            float4 vA = *(const float4*)pA[i];
            float4 vB = *(const float4*)pB[i];
            int eoff = frow[i]*TCS_LD + fk[i];
            split_store(vA, (__nv_bfloat16*)(sb + TCS_AHI) + eoff,
                             (__nv_bfloat16*)(sb + TCS_ALO) + eoff);
            split_store(vB, (__nv_bfloat16*)(sb + TCS_BHI) + eoff,
                             (__nv_bfloat16*)(sb + TCS_BLO) + eoff);
        }
    }
    __syncthreads();

    for (int kt = 0; kt < KT; kt++) {
        unsigned char* sb = sm + (kt & 1) * TCS_STAGE;

        float4 vA[2], vB[2];
        int havenext = (kt + 1 < KT);
        if (havenext) {
            int ko = (kt + 1) << 4;
#pragma unroll
            for (int i = 0; i < 2; i++) {
                vA[i] = *(const float4*)(pA[i] + ko);
                vB[i] = *(const float4*)(pB[i] + ko);
            }
        }

        wmma::fragment<wmma::matrix_a, 16, 16, 16, __nv_bfloat16, wmma::row_major> a_hi[2], a_lo[2];
        wmma::fragment<wmma::matrix_b, 16, 16, 16, __nv_bfloat16, wmma::col_major> b_hi[4], b_lo[4];
#pragma unroll
        for (int mi = 0; mi < 2; mi++) {
            const __nv_bfloat16* ah = (const __nv_bfloat16*)(sb + TCS_AHI) + (wm + mi*16)*TCS_LD;
            const __nv_bfloat16* al = (const __nv_bfloat16*)(sb + TCS_ALO) + (wm + mi*16)*TCS_LD;
            wmma::load_matrix_sync(a_hi[mi], ah, TCS_LD);
            wmma::load_matrix_sync(a_lo[mi], al, TCS_LD);
        }
#pragma unroll
        for (int nj = 0; nj < 4; nj++) {
            const __nv_bfloat16* bh = (const __nv_bfloat16*)(sb + TCS_BHI) + (wn + nj*16)*TCS_LD;
            const __nv_bfloat16* bl = (const __nv_bfloat16*)(sb + TCS_BLO) + (wn + nj*16)*TCS_LD;
            wmma::load_matrix_sync(b_hi[nj], bh, TCS_LD);
            wmma::load_matrix_sync(b_lo[nj], bl, TCS_LD);
        }

#pragma unroll
        for (int mi = 0; mi < 2; mi++)
#pragma unroll
            for (int nj = 0; nj < 4; nj++) {
                wmma::mma_sync(c_frag[mi][nj], a_hi[mi], b_hi[nj], c_frag[mi][nj]);
                wmma::mma_sync(c_frag[mi][nj], a_hi[mi], b_lo[nj], c_frag[mi][nj]);
                wmma::mma_sync(c_frag[mi][nj], a_lo[mi], b_hi[nj], c_frag[mi][nj]);
            }

        if (havenext) {
            unsigned char* sn = sm + ((kt + 1) & 1) * TCS_STAGE;
#pragma unroll
            for (int i = 0; i < 2; i++) {
                int eoff = frow[i]*TCS_LD + fk[i];
                split_store(vA[i], (__nv_bfloat16*)(sn + TCS_AHI) + eoff,
                                    (__nv_bfloat16*)(sn + TCS_ALO) + eoff);
                split_store(vB[i], (__nv_bfloat16*)(sn + TCS_BHI) + eoff,
                                    (__nv_bfloat16*)(sn + TCS_BLO) + eoff);
            }
        }
        __syncthreads();
    }

    // ---- epilogue: per-warp scratch (reuses stage smem; all mma reads done) ----
    float* scratch = (float*)(sm + warp * 1024);   // 16x16 fp32 = 1 KB per warp
#pragma unroll
    for (int mi = 0; mi < 2; mi++) {
        int rowbase = m0 + wm + mi*16;
#pragma unroll
        for (int nj = 0; nj < 4; nj++) {
            int colbase = n0 + wn + nj*16;
            wmma::store_matrix_sync(scratch, c_frag[mi][nj], 16, wmma::mem_row_major);
            __syncwarp();
#pragma unroll
            for (int e = 0; e < 8; e++) {
                int idx = lane + e*32;           // 0..255
                int r = idx >> 4, cc = idx & 15;
                int m = rowbase + r, n = colbase + cc;
                float v = scratch[idx] + bias[n];
                if (doGelu) v = gelu_exact(v);
                if (maskCol >= 0) v *= g_masks[(size_t)m * NEXP + maskCol];
                size_t ci = (size_t)m * ldc + n;
                if (res) v += res[ci];
                if (accumulate) C[ci] += v; else C[ci] = v;
            }
            __syncwarp();
        }
    }
}

// ---------------- attention scores: per (b,h), 64x64 tile, K=64 ----------------
__global__ void scores_kernel()
{
    int bh = blockIdx.z; int b = bh >> 4, h = bh & 15;
    int q0 = blockIdx.y * 64, k0 = blockIdx.x * 64;
    __shared__ float Qs[64][65], Ks[64][65];
    int tid = threadIdx.x;
    const float* qbase = g_qkv + ((size_t)(b*SEQ) + q0) * 3072 + h*64;
    const float* kbase = g_qkv + ((size_t)(b*SEQ) + k0) * 3072 + 1024 + h*64;
#pragma unroll
    for (int i = 0; i < 4; i++) {
        int lin = tid + i*256;            // float4 index
        int r = lin >> 4, c4 = (lin & 15) * 4;
        float4 qa = *(const float4*)(qbase + (size_t)r*3072 + c4);
        Qs[r][c4+0]=qa.x; Qs[r][c4+1]=qa.y; Qs[r][c4+2]=qa.z; Qs[r][c4+3]=qa.w;
        float4 ka = *(const float4*)(kbase + (size_t)r*3072 + c4);
        Ks[r][c4+0]=ka.x; Ks[r][c4+1]=ka.y; Ks[r][c4+2]=ka.z; Ks[r][c4+3]=ka.w;
    }
    __syncthreads();
    int tx = tid & 15, ty = tid >> 4;
    float acc[4][4];
#pragma unroll
    for (int i=0;i<4;i++)
#pragma unroll
        for (int j=0;j<4;j++) acc[i][j]=0.f;
#pragma unroll 8
    for (int k = 0; k < 64; k++) {
        float a[4], bb[4];
#pragma unroll
        for (int i=0;i<4;i++) a[i]  = Qs[ty*4+i][k];
#pragma unroll
        for (int j=0;j<4;j++) bb[j] = Ks[tx*4+j][k];
#pragma unroll
        for (int i=0;i<4;i++)
#pragma unroll
            for (int j=0;j<4;j++) acc[i][j] += a[i]*bb[j];
    }
    float* out = g_attn + ((size_t)bh*SEQ + q0)*SEQ + k0;
#pragma unroll
    for (int i=0;i<4;i++)
#pragma unroll
        for (int j=0;j<4;j++)
            out[(size_t)(ty*4+i)*SEQ + tx*4+j] = acc[i][j] * 0.125f;
}

// ---------------- softmax over last dim (512), one block per row ----------------
__global__ void softmax_kernel()
{
    size_t base = (size_t)blockIdx.x * SEQ;
    int t = threadIdx.x; // 256
    float v0 = g_attn[base+t], v1 = g_attn[base+t+256];
    __shared__ float red[256];
    red[t] = fmaxf(v0, v1); __syncthreads();
    for (int o = 128; o > 0; o >>= 1) {
        if (t < o) red[t] = fmaxf(red[t], red[t+o]);
        __syncthreads();
    }
    float mx = red[0]; __syncthreads();
    float e0 = expf(v0 - mx), e1 = expf(v1 - mx);
    red[t] = e0 + e1; __syncthreads();
    for (int o = 128; o > 0; o >>= 1) {
        if (t < o) red[t] += red[t+o];
        __syncthreads();
    }
    float inv = 1.0f / red[0];
    g_attn[base+t] = e0*inv; g_attn[base+t+256] = e1*inv;
}

// ---------------- attn mean over heads -> attn_weights ----------------
__global__ void attnmean_kernel(float* __restrict__ out)
{
    size_t lin = (size_t)blockIdx.x * 256 + threadIdx.x;  // over B*S*S
    int b = (int)(lin / ((size_t)SEQ*SEQ));
    size_t r = lin % ((size_t)SEQ*SEQ);
    const float* p = g_attn + (size_t)b*HEADS*SEQ*SEQ + r;
    float s = 0.f;
#pragma unroll
    for (int h = 0; h < HEADS; h++) s += p[(size_t)h*SEQ*SEQ];
    out[lin] = s * (1.0f/HEADS);
}

// ---------------- ctx = attn @ V per (b,h) ----------------
__global__ void ctx_kernel()
{
    int bh = blockIdx.y; int b = bh >> 4, h = bh & 15;
    int q0 = blockIdx.x * 64;
    __shared__ float As[16][64];  // As[k][q]
    __shared__ float Vs[16][64];  // Vs[k][d]
    const float* arow  = g_attn + ((size_t)bh*SEQ + q0) * SEQ;
    const float* vbase = g_qkv + (size_t)(b*SEQ) * 3072 + 2048 + h*64;
    int tid = threadIdx.x, tx = tid & 15, ty = tid >> 4;
    float acc[4][4];
#pragma unroll
    for (int i=0;i<4;i++)
#pragma unroll
        for (int j=0;j<4;j++) acc[i][j]=0.f;

    for (int k0 = 0; k0 < SEQ; k0 += 16) {
        {
            int q = tid >> 2, k4 = (tid & 3) * 4;
            float4 a4 = *(const float4*)(arow + (size_t)q*SEQ + k0 + k4);
            As[k4+0][q]=a4.x; As[k4+1][q]=a4.y; As[k4+2][q]=a4.z; As[k4+3][q]=a4.w;
            int k = tid >> 4, d4 = (tid & 15) * 4;
            float4 v4 = *(const float4*)(vbase + (size_t)(k0+k)*3072 + d4);
            *(float4*)&Vs[k][d4] = v4;
        }
        __syncthreads();
#pragma unroll
        for (int k = 0; k < 16; k++) {
            float a[4], bb[4];
#pragma unroll
            for (int i=0;i<4;i++) a[i]  = As[k][ty*4+i];
#pragma unroll
            for (int j=0;j<4;j++) bb[j] = Vs[k][tx*4+j];
#pragma unroll
            for (int i=0;i<4;i++)
#pragma unroll
                for (int j=0;j<4;j++) acc[i][j] += a[i]*bb[j];
        }
        __syncthreads();
    }
    float* out = g_ctx + ((size_t)(b*SEQ) + q0) * EMB + h*64;
#pragma unroll
    for (int i=0;i<4;i++)
#pragma unroll
        for (int j=0;j<4;j++)
            out[(size_t)(ty*4+i)*EMB + tx*4+j] = acc[i][j];
}

// ---------------- routers: one block per token ----------------
__global__ void zero_acc_kernel() { if (threadIdx.x < 12) g_acc[threadIdx.x] = 0.f; }

__global__ void router_kernel(const float* __restrict__ srw, const float* __restrict__ srb,
                              const float* __restrict__ irw, const float* __restrict__ irb,
                              float* __restrict__ smask, float* __restrict__ imask)
{
    int m = blockIdx.x, t = threadIdx.x;  // 128 threads
    const float* xr = g_xn2 + (size_t)m * EMB;
    float p[6] = {0,0,0,0,0,0};
    for (int e = t; e < EMB; e += 128) {
        float xv = xr[e];
        p[0] += xv * srw[e];
        p[1] += xv * srw[EMB + e];
        p[2] += xv * srw[2*EMB + e];
        p[3] += xv * srw[3*EMB + e];
        p[4] += xv * irw[e];
        p[5] += xv * irw[EMB + e];
    }
    __shared__ float red[6][128];
#pragma unroll
    for (int n = 0; n < 6; n++) red[n][t] = p[n];
    __syncthreads();
    for (int o = 64; o > 0; o >>= 1) {
        if (t < o)
#pragma unroll
            for (int n = 0; n < 6; n++) red[n][t] += red[n][t+o];
        __syncthreads();
    }
    if (t == 0) {
        float lg[6];
        for (int n = 0; n < 4; n++) lg[n] = red[n][0] + srb[n];
        lg[4] = red[4][0] + irb[0];
        lg[5] = red[5][0] + irb[1];
        float mx = lg[0];
        for (int n = 1; n < 4; n++) mx = fmaxf(mx, lg[n]);
        float pp[4], sum = 0.f;
        for (int n = 0; n < 4; n++) { pp[n] = expf(lg[n]-mx); sum += pp[n]; }
        float invs = 1.0f/sum;
        for (int n = 0; n < 4; n++) pp[n] *= invs;
        int i1 = 0;
        for (int n = 1; n < 4; n++) if (pp[n] > pp[i1]) i1 = n;
        int i2 = -1;
        for (int n = 0; n < 4; n++) if (n != i1 && (i2 < 0 || pp[n] > pp[i2])) i2 = n;
        float mxi = fmaxf(lg[4], lg[5]);
        float e4 = expf(lg[4]-mxi), e5 = expf(lg[5]-mxi);
        float si = 1.0f/(e4+e5);
        float pi0 = e4*si, pi1 = e5*si;
        for (int n = 0; n < 4; n++) {
            float mv = (n == i1 || n == i2) ? pp[n] : 0.f;
            g_masks[(size_t)m*NEXP + n] = mv;
            smask[(size_t)m*NS + n]     = mv;
        }
        g_masks[(size_t)m*NEXP + 4] = pi0; g_masks[(size_t)m*NEXP + 5] = pi1;
        imask[(size_t)m*NM + 0] = pi0;     imask[(size_t)m*NM + 1] = pi1;
        for (int n = 0; n < 4; n++) atomicAdd(&g_acc[n], pp[n]);
        atomicAdd(&g_acc[4], pi0); atomicAdd(&g_acc[5], pi1);
        atomicAdd(&g_acc[6+i1], 1.0f); atomicAdd(&g_acc[6+i2], 1.0f);
        atomicAdd(&g_acc[10], 1.0f);   atomicAdd(&g_acc[11], 1.0f);
    }
}

__global__ void loss_kernel(float* __restrict__ out)
{
    if (threadIdx.x == 0 && blockIdx.x == 0) {
        const float inv = 1.0f / (float)TOK;
        float ls = 0.f, li = 0.f;
        for (int n = 0; n < 4; n++) ls += (g_acc[n]*inv) * (g_acc[6+n]*inv);
        for (int n = 4; n < 6; n++) li += (g_acc[n]*inv) * (g_acc[6+n]*inv);
        out[0] = 4.0f*ls + 2.0f*li;
    }
}

__global__ void add_kernel()   // x2 = x1 + comb
{
    size_t i = (size_t)blockIdx.x * 256 + threadIdx.x;
    g_x2[i] = g_x1[i] + g_comb[i];
}

// ---------------- launcher ----------------
extern "C" void kernel_launch(void* const* d_in, const int* in_sizes, int n_in,
                              void* d_out, int out_size)
{
    const float* x   = (const float*)d_in[0];
    const float* n1w = (const float*)d_in[1];
    const float* n1b = (const float*)d_in[2];
    const float* n2w = (const float*)d_in[3];
    const float* n2b = (const float*)d_in[4];
    const float* ipw = (const float*)d_in[5];
    const float* ipb = (const float*)d_in[6];
    const float* opw = (const float*)d_in[7];
    const float* opb = (const float*)d_in[8];
    const float* srw = (const float*)d_in[9];
    const float* srb = (const float*)d_in[10];
    const float* irw = (const float*)d_in[11];
    const float* irb = (const float*)d_in[12];
    const float* ew1 = (const float*)d_in[13];
    const float* eb1 = (const float*)d_in[14];
    const float* ew2 = (const float*)d_in[15];
    const float* eb2 = (const float*)d_in[16];
    const float* fw1 = (const float*)d_in[17];
    const float* fb1 = (const float*)d_in[18];
    const float* fw2 = (const float*)d_in[19];
    const float* fb2 = (const float*)d_in[20];

    float* out      = (float*)d_out;
    float* out_x    = out;
    float* out_loss = out + OFF_LOSS;
    float* out_sm   = out + OFF_SM;
    float* out_im   = out + OFF_IM;
    float* out_aw   = out + OFF_AW;

    // 1) LN1: xn = LN(x)
    ln_kernel<<<TOK, 256>>>(x, BUF_NONE, n1w, n1b, BUF_XN);

    // 2) QKV = xn @ ipw^T + ipb    [4096,3072], K=1024
    gemm_tc_kernel<<<dim3(3072/128, TOK/128), 256>>>(
        BUF_XN, EMB, ipw, EMB, ipb, nullptr, BUF_QKV, 3*EMB, EMB,
        nullptr, BUF_NONE, -1, 0, 0);

    // 3) scores
    scores_kernel<<<dim3(SEQ/64, SEQ/64, BATCH*HEADS), 256>>>();

    // 4) softmax in place
    softmax_kernel<<<BATCH*HEADS*SEQ, 256>>>();

    // 5) attn mean over heads -> output
    attnmean_kernel<<<(BATCH*SEQ*SEQ)/256, 256>>>(out_aw);

    // 6) ctx = attn @ V
    ctx_kernel<<<dim3(SEQ/64, BATCH*HEADS), 256>>>();

    // 7) x1 = x + ctx @ opw^T + opb
    gemm_tc_kernel<<<dim3(EMB/128, TOK/128), 256>>>(
        BUF_CTX, EMB, opw, EMB, opb, nullptr, BUF_X1, EMB, EMB,
        x, BUF_NONE, -1, 0, 0);

    // 8) LN2: xn2 = LN(x1)
    ln_kernel<<<TOK, 256>>>(nullptr, BUF_X1, n2w, n2b, BUF_XN2);

    // 9-11) routers + loss
    zero_acc_kernel<<<1, 32>>>();
    router_kernel<<<TOK, 128>>>(srw, srb, irw, irb, out_sm, out_im);
    loss_kernel<<<1, 32>>>(out_loss);

    // 12) experts (dense, masked-accumulated combine)
    for (int n = 0; n < NEXP; n++) {
        const float* w1 = ew1 + (size_t)n * DFF * EMB;
        const float* b1 = eb1 + (size_t)n * DFF;
        const float* w2 = ew2 + (size_t)n * EMB * DFF;
        const float* b2 = eb2 + (size_t)n * EMB;
        // h = gelu(xn2 @ w1^T + b1)   [4096,4096], K=1024
        gemm_tc_kernel<<<dim3(DFF/128, TOK/128), 256>>>(
            BUF_XN2, EMB, w1, EMB, b1, nullptr, BUF_H, DFF, EMB,
            nullptr, BUF_NONE, -1, 1, 0);
        // comb (+)= mask[:,n] * (h @ w2^T + b2)   [4096,1024], K=4096
        gemm_tc_kernel<<<dim3(EMB/128, TOK/128), 256>>>(
            BUF_H, DFF, w2, DFF, b2, nullptr, BUF_COMB, EMB, DFF,
            nullptr, BUF_NONE, n, 0, n > 0 ? 1 : 0);
    }

    // 13) x2 = x1 + comb
    add_kernel<<<(TOK*EMB)/256, 256>>>();

    // 14) LN3 (reuses norm2 params)
    ln_kernel<<<TOK, 256>>>(nullptr, BUF_X2, n2w, n2b, BUF_XN3);

    // 15) fh = gelu(xn3 @ fw1^T + fb1)   [4096,4096], K=1024
    gemm_tc_kernel<<<dim3(DFF/128, TOK/128), 256>>>(
        BUF_XN3, EMB, fw1, EMB, fb1, nullptr, BUF_H, DFF, EMB,
        nullptr, BUF_NONE, -1, 1, 0);

    // 16) out_x = x2 + fh @ fw2^T + fb2   [4096,1024], K=4096
    gemm_tc_kernel<<<dim3(EMB/128, TOK/128), 256>>>(
        BUF_H, DFF, fw2, DFF, fb2, out_x, BUF_NONE, EMB, DFF,
        nullptr, BUF_X2, -1, 0, 0);
}